// round 5
// baseline (speedup 1.0000x reference)
#include <cuda_runtime.h>

#define N_NODES 200000
#define C_IN 5

// Scratch in __device__ globals (no allocation allowed)
__device__ int    g_cnt[N_NODES];     // in-degree (dst counts), excl. self-loop
__device__ float2 g_hs[N_NODES];      // (x @ W) * dinv
__device__ float  g_dinv[N_NODES];    // rsqrt(deg)
__device__ float2 g_acc[N_NODES];     // sum of hs[src] per dst (init = self-loop term)

__device__ __forceinline__ void red_add_v2(float2* addr, float a, float b) {
    asm volatile("red.global.add.v2.f32 [%0], {%1, %2};"
                 :: "l"(addr), "f"(a), "f"(b)
                 : "memory");
}

// 4 edges/thread, int4 loads; 1 random wavefront per edge.
__global__ void __launch_bounds__(256) k_count(const int4* __restrict__ dst4, int E4) {
    int i = blockIdx.x * blockDim.x + threadIdx.x;
    if (i >= E4) return;
    int4 d = dst4[i];
    atomicAdd(&g_cnt[d.x], 1);
    atomicAdd(&g_cnt[d.y], 1);
    atomicAdd(&g_cnt[d.z], 1);
    atomicAdd(&g_cnt[d.w], 1);
}

// One pass: h = x@W, dinv, hs, acc init (self-loop term).
__global__ void k_prep(const float* __restrict__ x,
                       const float* __restrict__ W,
                       int n) {
    int i = blockIdx.x * blockDim.x + threadIdx.x;
    if (i >= n) return;
    const float* xr = x + (size_t)i * C_IN;
    float x0 = xr[0], x1 = xr[1], x2 = xr[2], x3 = xr[3], x4 = xr[4];
    float h0 = x0 * W[0] + x1 * W[2] + x2 * W[4] + x3 * W[6] + x4 * W[8];
    float h1 = x0 * W[1] + x1 * W[3] + x2 * W[5] + x3 * W[7] + x4 * W[9];
    float dinv = rsqrtf((float)(g_cnt[i] + 1));   // +1 self-loop
    float2 hs = make_float2(h0 * dinv, h1 * dinv);
    g_hs[i] = hs;
    g_dinv[i] = dinv;
    g_acc[i] = hs;   // self-loop contribution (dinv[dst] applied at finalize)
}

// 4 edges/thread: 2 random wavefronts per edge (gather + fused v2 RED).
__global__ void __launch_bounds__(256) k_scatter(const int4* __restrict__ src4,
                                                 const int4* __restrict__ dst4,
                                                 int E4) {
    int i = blockIdx.x * blockDim.x + threadIdx.x;
    if (i >= E4) return;
    int4 s = src4[i];
    int4 d = dst4[i];
    float2 a = g_hs[s.x];
    float2 b = g_hs[s.y];
    float2 c = g_hs[s.z];
    float2 e = g_hs[s.w];
    red_add_v2(&g_acc[d.x], a.x, a.y);
    red_add_v2(&g_acc[d.y], b.x, b.y);
    red_add_v2(&g_acc[d.z], c.x, c.y);
    red_add_v2(&g_acc[d.w], e.x, e.y);
}

__global__ void k_final(const float* __restrict__ x,
                        const float* __restrict__ b,
                        float* __restrict__ out,
                        int n) {
    int i = blockIdx.x * blockDim.x + threadIdx.x;
    if (i >= n) return;
    float2 a = g_acc[i];
    float dinv = g_dinv[i];
    float b0 = b[0], b1 = b[1];
    float acc0 = (a.x * dinv + b0) * 0.01f;
    float acc1 = (a.y * dinv + b1) * 0.01f;
    const float* xr = x + (size_t)i * C_IN;
    float v0 = fminf(fmaxf(xr[2] + acc0, -0.1f), 0.1f);
    float v1 = fminf(fmaxf(xr[3] + acc1, -0.1f), 0.1f);
    float p0 = fminf(fmaxf(xr[0] + v0, -1.0f), 1.0f);
    float p1 = fminf(fmaxf(xr[1] + v1, -1.0f), 1.0f);
    float* orow = out + (size_t)i * C_IN;
    orow[0] = p0;
    orow[1] = p1;
    orow[2] = v0;
    orow[3] = v1;
    orow[4] = xr[4];
}

extern "C" void kernel_launch(void* const* d_in, const int* in_sizes, int n_in,
                              void* d_out, int out_size) {
    const float* x  = (const float*)d_in[0];   // [N,5]
    const int*   ei = (const int*)d_in[1];     // [2,E]: src row then dst row
    const float* W  = (const float*)d_in[2];   // [5,2]
    const float* b  = (const float*)d_in[3];   // [2]
    float* out = (float*)d_out;

    int n = in_sizes[0] / C_IN;     // 200000
    int E = in_sizes[1] / 2;        // 12800000 (divisible by 4)
    const int* src = ei;
    const int* dst = ei + E;
    int E4 = E / 4;

    const int T = 256;
    int gN  = (n + T - 1) / T;
    int gE4 = (E4 + T - 1) / T;

    // Zero counts via memset node (no kernel).
    void* cnt_ptr = nullptr;
    cudaGetSymbolAddress(&cnt_ptr, g_cnt);
    cudaMemsetAsync(cnt_ptr, 0, (size_t)n * sizeof(int));

    k_count<<<gE4, T>>>((const int4*)dst, E4);
    k_prep<<<gN, T>>>(x, W, n);
    k_scatter<<<gE4, T>>>((const int4*)src, (const int4*)dst, E4);
    k_final<<<gN, T>>>(x, b, out, n);
}

// round 6
// speedup vs baseline: 1.0217x; 1.0217x over previous
#include <cuda_runtime.h>

#define N_NODES 200000
#define C_IN 5

// Scratch in __device__ globals (zero-initialized at module load; k_final
// re-zeroes g_cnt each call so every invocation sees zeros -- deterministic).
__device__ int    g_cnt[N_NODES];     // in-degree (dst counts), excl. self-loop
__device__ float2 g_hs[N_NODES];      // (x @ W) * dinv
__device__ float  g_dinv[N_NODES];    // rsqrt(deg)
__device__ float2 g_acc[N_NODES];     // sum of hs[src] per dst (init = self-loop term)

__device__ __forceinline__ void red_add_v2(float2* addr, float a, float b) {
    asm volatile("red.global.add.v2.f32 [%0], {%1, %2};"
                 :: "l"(addr), "f"(a), "f"(b)
                 : "memory");
}

// Streaming (evict-first) int4 load: don't pollute L1 with one-touch index data.
__device__ __forceinline__ int4 ldg_cs_int4(const int4* p) {
    int4 v;
    asm volatile("ld.global.cs.v4.s32 {%0,%1,%2,%3}, [%4];"
                 : "=r"(v.x), "=r"(v.y), "=r"(v.z), "=r"(v.w) : "l"(p));
    return v;
}

// Cache-all gather of float2 (keep hs table resident in L1).
__device__ __forceinline__ float2 ldg_ca_f2(const float2* p) {
    float2 v;
    asm volatile("ld.global.ca.v2.f32 {%0,%1}, [%2];"
                 : "=f"(v.x), "=f"(v.y) : "l"(p));
    return v;
}

// 4 edges/thread, streaming index loads; 1 random RED per edge.
__global__ void __launch_bounds__(256) k_count(const int4* __restrict__ dst4, int E4) {
    int i = blockIdx.x * blockDim.x + threadIdx.x;
    if (i >= E4) return;
    int4 d = ldg_cs_int4(dst4 + i);
    atomicAdd(&g_cnt[d.x], 1);
    atomicAdd(&g_cnt[d.y], 1);
    atomicAdd(&g_cnt[d.z], 1);
    atomicAdd(&g_cnt[d.w], 1);
}

// One pass: h = x@W, dinv, hs, acc init (self-loop term).
__global__ void k_prep(const float* __restrict__ x,
                       const float* __restrict__ W,
                       int n) {
    int i = blockIdx.x * blockDim.x + threadIdx.x;
    if (i >= n) return;
    const float* xr = x + (size_t)i * C_IN;
    float x0 = xr[0], x1 = xr[1], x2 = xr[2], x3 = xr[3], x4 = xr[4];
    float h0 = x0 * W[0] + x1 * W[2] + x2 * W[4] + x3 * W[6] + x4 * W[8];
    float h1 = x0 * W[1] + x1 * W[3] + x2 * W[5] + x3 * W[7] + x4 * W[9];
    float dinv = rsqrtf((float)(g_cnt[i] + 1));   // +1 self-loop
    float2 hs = make_float2(h0 * dinv, h1 * dinv);
    g_hs[i] = hs;
    g_dinv[i] = dinv;
    g_acc[i] = hs;   // self-loop contribution (dinv[dst] applied at finalize)
}

// 4 edges/thread: random gather (.ca) + fused v2 RED per edge.
__global__ void __launch_bounds__(256) k_scatter(const int4* __restrict__ src4,
                                                 const int4* __restrict__ dst4,
                                                 int E4) {
    int i = blockIdx.x * blockDim.x + threadIdx.x;
    if (i >= E4) return;
    int4 s = ldg_cs_int4(src4 + i);
    int4 d = ldg_cs_int4(dst4 + i);
    float2 a = ldg_ca_f2(&g_hs[s.x]);
    float2 b = ldg_ca_f2(&g_hs[s.y]);
    float2 c = ldg_ca_f2(&g_hs[s.z]);
    float2 e = ldg_ca_f2(&g_hs[s.w]);
    red_add_v2(&g_acc[d.x], a.x, a.y);
    red_add_v2(&g_acc[d.y], b.x, b.y);
    red_add_v2(&g_acc[d.z], c.x, c.y);
    red_add_v2(&g_acc[d.w], e.x, e.y);
}

__global__ void k_final(const float* __restrict__ x,
                        const float* __restrict__ b,
                        float* __restrict__ out,
                        int n) {
    int i = blockIdx.x * blockDim.x + threadIdx.x;
    if (i >= n) return;
    float2 a = g_acc[i];
    float dinv = g_dinv[i];
    g_cnt[i] = 0;                      // re-arm counts for the next call
    float b0 = b[0], b1 = b[1];
    float acc0 = (a.x * dinv + b0) * 0.01f;
    float acc1 = (a.y * dinv + b1) * 0.01f;
    const float* xr = x + (size_t)i * C_IN;
    float v0 = fminf(fmaxf(xr[2] + acc0, -0.1f), 0.1f);
    float v1 = fminf(fmaxf(xr[3] + acc1, -0.1f), 0.1f);
    float p0 = fminf(fmaxf(xr[0] + v0, -1.0f), 1.0f);
    float p1 = fminf(fmaxf(xr[1] + v1, -1.0f), 1.0f);
    float* orow = out + (size_t)i * C_IN;
    orow[0] = p0;
    orow[1] = p1;
    orow[2] = v0;
    orow[3] = v1;
    orow[4] = xr[4];
}

extern "C" void kernel_launch(void* const* d_in, const int* in_sizes, int n_in,
                              void* d_out, int out_size) {
    const float* x  = (const float*)d_in[0];   // [N,5]
    const int*   ei = (const int*)d_in[1];     // [2,E]: src row then dst row
    const float* W  = (const float*)d_in[2];   // [5,2]
    const float* b  = (const float*)d_in[3];   // [2]
    float* out = (float*)d_out;

    int n = in_sizes[0] / C_IN;     // 200000
    int E = in_sizes[1] / 2;        // 12800000 (divisible by 4)
    const int* src = ei;
    const int* dst = ei + E;
    int E4 = E / 4;

    const int T = 256;
    int gN  = (n + T - 1) / T;
    int gE4 = (E4 + T - 1) / T;

    k_count<<<gE4, T>>>((const int4*)dst, E4);
    k_prep<<<gN, T>>>(x, W, n);
    k_scatter<<<gE4, T>>>((const int4*)src, (const int4*)dst, E4);
    k_final<<<gN, T>>>(x, b, out, n);
}

// round 7
// speedup vs baseline: 1.0226x; 1.0009x over previous
#include <cuda_runtime.h>

#define N_NODES 200000
#define C_IN 5

// Scratch in __device__ globals (zero-initialized at module load; k_final
// re-zeroes g_cnt each call so every invocation sees zeros -- deterministic).
__device__ int    g_cnt[N_NODES];     // in-degree (dst counts), excl. self-loop
__device__ float2 g_hs[N_NODES];      // (x @ W) * dinv
__device__ float  g_dinv[N_NODES];    // rsqrt(deg)
__device__ float2 g_acc[N_NODES];     // sum of hs[src] per dst (init = self-loop term)

__device__ __forceinline__ void red_add_v2(float2* addr, float a, float b) {
    asm volatile("red.global.add.v2.f32 [%0], {%1, %2};"
                 :: "l"(addr), "f"(a), "f"(b)
                 : "memory");
}

// Streaming (evict-first) int4 load: don't pollute L1 with one-touch index data.
__device__ __forceinline__ int4 ldg_cs_int4(const int4* p) {
    int4 v;
    asm volatile("ld.global.cs.v4.s32 {%0,%1,%2,%3}, [%4];"
                 : "=r"(v.x), "=r"(v.y), "=r"(v.z), "=r"(v.w) : "l"(p));
    return v;
}

// Cache-all gather of float2 (keep hs table resident in L1).
__device__ __forceinline__ float2 ldg_ca_f2(const float2* p) {
    float2 v;
    asm volatile("ld.global.ca.v2.f32 {%0,%1}, [%2];"
                 : "=f"(v.x), "=f"(v.y) : "l"(p));
    return v;
}

// 4 edges/thread; 1 random RED per edge. Trigger fires once all blocks' atomics issued.
__global__ void __launch_bounds__(256) k_count(const int4* __restrict__ dst4, int E4) {
    int i = blockIdx.x * blockDim.x + threadIdx.x;
    if (i < E4) {
        int4 d = ldg_cs_int4(dst4 + i);
        atomicAdd(&g_cnt[d.x], 1);
        atomicAdd(&g_cnt[d.y], 1);
        atomicAdd(&g_cnt[d.z], 1);
        atomicAdd(&g_cnt[d.w], 1);
    }
    cudaTriggerProgrammaticLaunchCompletion();
}

// One pass: h = x@W, dinv, hs, acc init (self-loop term). PDL-gated on k_count.
__global__ void k_prep(const float* __restrict__ x,
                       const float* __restrict__ W,
                       int n) {
    int i = blockIdx.x * blockDim.x + threadIdx.x;
    cudaGridDependencySynchronize();
    if (i < n) {
        const float* xr = x + (size_t)i * C_IN;
        float x0 = xr[0], x1 = xr[1], x2 = xr[2], x3 = xr[3], x4 = xr[4];
        float h0 = x0 * W[0] + x1 * W[2] + x2 * W[4] + x3 * W[6] + x4 * W[8];
        float h1 = x0 * W[1] + x1 * W[3] + x2 * W[5] + x3 * W[7] + x4 * W[9];
        float dinv = rsqrtf((float)(g_cnt[i] + 1));   // +1 self-loop
        float2 hs = make_float2(h0 * dinv, h1 * dinv);
        g_hs[i] = hs;
        g_dinv[i] = dinv;
        g_acc[i] = hs;   // self-loop contribution (dinv[dst] applied at finalize)
    }
    cudaTriggerProgrammaticLaunchCompletion();
}

// 4 edges/thread: random gather (.ca) + fused v2 RED per edge. PDL-gated on k_prep.
__global__ void __launch_bounds__(256) k_scatter(const int4* __restrict__ src4,
                                                 const int4* __restrict__ dst4,
                                                 int E4) {
    int i = blockIdx.x * blockDim.x + threadIdx.x;
    cudaGridDependencySynchronize();
    if (i < E4) {
        int4 s = ldg_cs_int4(src4 + i);
        int4 d = ldg_cs_int4(dst4 + i);
        float2 a = ldg_ca_f2(&g_hs[s.x]);
        float2 b = ldg_ca_f2(&g_hs[s.y]);
        float2 c = ldg_ca_f2(&g_hs[s.z]);
        float2 e = ldg_ca_f2(&g_hs[s.w]);
        red_add_v2(&g_acc[d.x], a.x, a.y);
        red_add_v2(&g_acc[d.y], b.x, b.y);
        red_add_v2(&g_acc[d.z], c.x, c.y);
        red_add_v2(&g_acc[d.w], e.x, e.y);
    }
    cudaTriggerProgrammaticLaunchCompletion();
}

// PDL-gated on k_scatter.
__global__ void k_final(const float* __restrict__ x,
                        const float* __restrict__ b,
                        float* __restrict__ out,
                        int n) {
    int i = blockIdx.x * blockDim.x + threadIdx.x;
    cudaGridDependencySynchronize();
    if (i >= n) return;
    float2 a = g_acc[i];
    float dinv = g_dinv[i];
    g_cnt[i] = 0;                      // re-arm counts for the next call
    float b0 = b[0], b1 = b[1];
    float acc0 = (a.x * dinv + b0) * 0.01f;
    float acc1 = (a.y * dinv + b1) * 0.01f;
    const float* xr = x + (size_t)i * C_IN;
    float v0 = fminf(fmaxf(xr[2] + acc0, -0.1f), 0.1f);
    float v1 = fminf(fmaxf(xr[3] + acc1, -0.1f), 0.1f);
    float p0 = fminf(fmaxf(xr[0] + v0, -1.0f), 1.0f);
    float p1 = fminf(fmaxf(xr[1] + v1, -1.0f), 1.0f);
    float* orow = out + (size_t)i * C_IN;
    orow[0] = p0;
    orow[1] = p1;
    orow[2] = v0;
    orow[3] = v1;
    orow[4] = xr[4];
}

template <typename... Args>
static inline void launch_pdl(void (*kern)(Args...), int grid, int block,
                              Args... args) {
    cudaLaunchConfig_t cfg = {};
    cfg.gridDim = dim3(grid);
    cfg.blockDim = dim3(block);
    cudaLaunchAttribute attr[1];
    attr[0].id = cudaLaunchAttributeProgrammaticStreamSerialization;
    attr[0].val.programmaticStreamSerializationAllowed = 1;
    cfg.attrs = attr;
    cfg.numAttrs = 1;
    cudaLaunchKernelEx(&cfg, kern, args...);
}

extern "C" void kernel_launch(void* const* d_in, const int* in_sizes, int n_in,
                              void* d_out, int out_size) {
    const float* x  = (const float*)d_in[0];   // [N,5]
    const int*   ei = (const int*)d_in[1];     // [2,E]: src row then dst row
    const float* W  = (const float*)d_in[2];   // [5,2]
    const float* b  = (const float*)d_in[3];   // [2]
    float* out = (float*)d_out;

    int n = in_sizes[0] / C_IN;     // 200000
    int E = in_sizes[1] / 2;        // 12800000 (divisible by 4)
    const int* src = ei;
    const int* dst = ei + E;
    int E4 = E / 4;

    const int T = 256;
    int gN  = (n + T - 1) / T;
    int gE4 = (E4 + T - 1) / T;

    k_count<<<gE4, T>>>((const int4*)dst, E4);
    launch_pdl(k_prep, gN, T, x, W, n);
    launch_pdl(k_scatter, gE4, T, (const int4*)src, (const int4*)dst, E4);
    launch_pdl(k_final, gN, T, x, b, out, n);
}